// round 3
// baseline (speedup 1.0000x reference)
#include <cuda_runtime.h>

#define BSEQ 512
#define LSEQ 512
#define AA   20
#define CCH  8
#define NREST 8
#define XPAD 21              // x_sh row pitch: gcd(21,32)=1 -> conflict-free

// Precomputed: effective conv map (transposed, [c][p]) and U = I + V
__device__ float g_W[CCH][LSEQ];
__device__ float g_U[AA * AA];

// ---------------------------------------------------------------------------
// Precompute kernel: blocks 0..7 -> one channel of W_eff via the adjoint of
// the conv+pool pipeline; block 8 -> U; blocks 9..168 -> zero d_out (so the
// main kernel's half-block atomics have a clean base).
// ---------------------------------------------------------------------------
template<int LEN2>
__device__ __forceinline__ void adj_layer(const float (*cur)[256],
                                          float (*nxt)[256],
                                          const float* __restrict__ w) {
    for (int idx = threadIdx.x; idx < CCH * LEN2; idx += blockDim.x) {
        const int i = idx / LEN2;
        const int p = idx % LEN2;
        float acc = 0.f;
        #pragma unroll
        for (int o = 0; o < CCH; ++o) {
            #pragma unroll
            for (int k = 0; k < 3; ++k) {
                const int q = p - k + 1;
                if (q >= 0 && q < LEN2)
                    acc += w[(o * CCH + i) * 3 + k] * 0.5f * cur[o][q >> 1];
            }
        }
        nxt[i][p] = acc;
    }
    __syncthreads();
}

__global__ void __launch_bounds__(256)
precompute_kernel(const float* __restrict__ lpm,
                  const float* __restrict__ pm,
                  const float* __restrict__ w_first,
                  const float* __restrict__ w_rest,
                  float* __restrict__ out) {
    const int blk = blockIdx.x;
    const int tid = threadIdx.x;

    if (blk < CCH) {
        __shared__ float bufA[CCH][256];
        __shared__ float bufB[CCH][256];
        __shared__ float wsh[NREST * CCH * CCH * 3];

        for (int i = tid; i < NREST * CCH * CCH * 3; i += blockDim.x)
            wsh[i] = w_rest[i];
        if (tid < CCH) bufA[tid][0] = (tid == blk) ? 1.f : 0.f;
        __syncthreads();

        float (*cur)[256] = bufA;
        float (*nxt)[256] = bufB;
        float (*tmp)[256];
        #define STEP(L2, LI) \
            adj_layer<L2>(cur, nxt, wsh + (LI) * CCH * CCH * 3); \
            tmp = cur; cur = nxt; nxt = tmp;
        STEP(2, 7)  STEP(4, 6)  STEP(8, 5)   STEP(16, 4)
        STEP(32, 3) STEP(64, 2) STEP(128, 1) STEP(256, 0)
        #undef STEP

        for (int p = tid; p < LSEQ; p += blockDim.x) {
            float acc = 0.f;
            #pragma unroll
            for (int o = 0; o < CCH; ++o) {
                #pragma unroll
                for (int k = 0; k < 3; ++k) {
                    const int q = p - k + 1;
                    if (q >= 0 && q < LSEQ)
                        acc += w_first[o * 3 + k] * 0.5f * cur[o][q >> 1];
                }
            }
            g_W[blk][p] = acc;            // transposed layout [c][p]
        }
    } else if (blk == CCH) {
        // U[a][i] = delta(a,i) + V[a][i]
        for (int idx = tid; idx < AA * AA; idx += blockDim.x) {
            const int a = idx / AA, i = idx % AA;
            float v = (a == i) ? 1.f : 0.f;
            if (i != a && i != AA - 1) {
                const int r = (a < i) ? a : i;
                const int c = (a < i) ? i : a;
                float l = lpm[r * AA + c];
                l = fminf(fmaxf(l, 1e-3f), 1.f);
                v = l * pm[r * AA + c];
            }
            g_U[idx] = v;
        }
    } else {
        // zero d_out: blocks 9..168, each clears 128 float4 (512 floats)
        const int z = blk - (CCH + 1);          // 0..159
        if (tid < 128)
            reinterpret_cast<float4*>(out)[z * 128 + tid] =
                make_float4(0.f, 0.f, 0.f, 0.f);
    }
}

// ---------------------------------------------------------------------------
// Main kernel: grid 1024 = 512 sequences x 2 halves of 256 positions.
// Dense g = X^T W on the half, U-contract, atomicAdd into out.
// 256 threads = 8 warps; warp (g = w>>1, h = w&1) owns the (5a x 4c) tile
// rows a in [5g,5g+5), cols c in [4h,4h+4), full K=256 per warp.
// ---------------------------------------------------------------------------
__global__ void __launch_bounds__(256)
main_kernel(const float* __restrict__ x, float* __restrict__ out) {
    __shared__ float x_sh[256 * XPAD];      // ~21 KB, row-major, pad 21
    __shared__ float W_sh[CCH * 256];       // 8 KB, [c][p]
    __shared__ float U_sh[AA * AA];
    __shared__ float g_sh[AA][CCH];

    const int bi   = blockIdx.x;
    const int b    = bi >> 1;
    const int half = bi & 1;
    const int tid  = threadIdx.x;
    const int s    = tid & 31;
    const int w    = tid >> 5;
    const int gq   = w >> 1;                // a-group 0..3
    const int h    = w & 1;                 // c-half 0..1

    // Stage W chunk [8][256] (stride-1 rows) and U.
    {
        const float4* Wg = reinterpret_cast<const float4*>(g_W);
        for (int i = tid; i < CCH * 64; i += 256) {      // 512 float4
            const int c = i >> 6, p4 = i & 63;
            reinterpret_cast<float4*>(W_sh)[c * 64 + p4] =
                Wg[c * 128 + half * 64 + p4];
        }
        for (int i = tid; i < AA * AA; i += 256) U_sh[i] = g_U[i];
    }

    // Stage x half-chunk: coalesced float4 loads, scatter into padded rows.
    {
        const float4* xg = reinterpret_cast<const float4*>(x)
                         + (size_t)b * 2560 + half * 1280;
        #pragma unroll
        for (int it = 0; it < 5; ++it) {
            const int i = tid + it * 256;    // float4 index, < 1280
            const float4 v = xg[i];
            const int p  = i / 5;            // local position
            const int a0 = (i - p * 5) * 4;
            float* d = &x_sh[p * XPAD + a0];
            d[0] = v.x; d[1] = v.y; d[2] = v.z; d[3] = v.w;
        }
    }
    __syncthreads();

    float acc[5][4];
    #pragma unroll
    for (int m = 0; m < 5; ++m)
        #pragma unroll
        for (int n = 0; n < 4; ++n) acc[m][n] = 0.f;

    const float* xp = &x_sh[s * XPAD + gq * 5];
    const float* wp = &W_sh[(h * 4) * 256 + s];
    #pragma unroll
    for (int j = 0; j < 8; ++j) {           // p = 32*j + s
        float xr[5], wr[4];
        #pragma unroll
        for (int m = 0; m < 5; ++m) xr[m] = xp[m];
        #pragma unroll
        for (int n = 0; n < 4; ++n) wr[n] = wp[n * 256];
        #pragma unroll
        for (int m = 0; m < 5; ++m)
            #pragma unroll
            for (int n = 0; n < 4; ++n)
                acc[m][n] += xr[m] * wr[n];
        xp += 32 * XPAD;
        wp += 32;
    }

    // Butterfly reduce over the 32 lanes (p within the warp's K).
    #pragma unroll
    for (int m = 0; m < 5; ++m)
        #pragma unroll
        for (int n = 0; n < 4; ++n)
            #pragma unroll
            for (int off = 16; off; off >>= 1)
                acc[m][n] += __shfl_xor_sync(0xffffffffu, acc[m][n], off);

    if (s == 0) {
        #pragma unroll
        for (int m = 0; m < 5; ++m)
            #pragma unroll
            for (int n = 0; n < 4; ++n)
                g_sh[gq * 5 + m][h * 4 + n] = acc[m][n];
    }
    __syncthreads();

    // out[b,i,c] += sum_a U[a][i] * g[a][c]   (2 halves combine via atomics)
    if (tid < AA * CCH) {
        const int i = tid >> 3;
        const int c = tid & 7;
        float r = 0.f;
        #pragma unroll
        for (int a = 0; a < AA; ++a)
            r += U_sh[a * AA + i] * g_sh[a][c];
        atomicAdd(&out[(size_t)b * (AA * CCH) + tid], r);
    }
}

// ---------------------------------------------------------------------------
extern "C" void kernel_launch(void* const* d_in, const int* in_sizes, int n_in,
                              void* d_out, int out_size) {
    const float* x       = (const float*)d_in[0];
    const float* lpm     = (const float*)d_in[2];
    const float* pm      = (const float*)d_in[3];
    const float* w_first = (const float*)d_in[4];
    const float* w_rest  = (const float*)d_in[5];
    float* out = (float*)d_out;

    precompute_kernel<<<CCH + 1 + 160, 256>>>(lpm, pm, w_first, w_rest, out);
    main_kernel<<<BSEQ * 2, 256>>>(x, out);
}

// round 4
// speedup vs baseline: 1.0952x; 1.0952x over previous
#include <cuda_runtime.h>

#define BSEQ 512
#define LSEQ 512
#define AA   20
#define CCH  8
#define NREST 8
#define XPAD 21              // x_sh row pitch: gcd(21,32)=1 -> conflict-free

// Precomputed: effective conv map (transposed, [c][p]) and U = I + V
__device__ float g_W[CCH][LSEQ];
__device__ float g_U[AA * AA];

// ---------------------------------------------------------------------------
// Precompute kernel: blocks 0..7 -> one channel of W_eff (adjoint of the
// conv+pool pipeline); block 8 -> U; blocks 9..168 -> zero d_out.
// ---------------------------------------------------------------------------
template<int LEN2>
__device__ __forceinline__ void adj_layer(const float (*cur)[256],
                                          float (*nxt)[256],
                                          const float* __restrict__ w) {
    for (int idx = threadIdx.x; idx < CCH * LEN2; idx += blockDim.x) {
        const int i = idx / LEN2;
        const int p = idx % LEN2;
        float acc = 0.f;
        #pragma unroll
        for (int o = 0; o < CCH; ++o) {
            #pragma unroll
            for (int k = 0; k < 3; ++k) {
                const int q = p - k + 1;
                if (q >= 0 && q < LEN2)
                    acc += w[(o * CCH + i) * 3 + k] * 0.5f * cur[o][q >> 1];
            }
        }
        nxt[i][p] = acc;
    }
    __syncthreads();
}

__global__ void __launch_bounds__(256)
precompute_kernel(const float* __restrict__ lpm,
                  const float* __restrict__ pm,
                  const float* __restrict__ w_first,
                  const float* __restrict__ w_rest,
                  float* __restrict__ out) {
    const int blk = blockIdx.x;
    const int tid = threadIdx.x;

    if (blk < CCH) {
        __shared__ float bufA[CCH][256];
        __shared__ float bufB[CCH][256];
        __shared__ float wsh[NREST * CCH * CCH * 3];

        for (int i = tid; i < NREST * CCH * CCH * 3; i += blockDim.x)
            wsh[i] = w_rest[i];
        if (tid < CCH) bufA[tid][0] = (tid == blk) ? 1.f : 0.f;
        __syncthreads();

        float (*cur)[256] = bufA;
        float (*nxt)[256] = bufB;
        float (*tmp)[256];
        #define STEP(L2, LI) \
            adj_layer<L2>(cur, nxt, wsh + (LI) * CCH * CCH * 3); \
            tmp = cur; cur = nxt; nxt = tmp;
        STEP(2, 7)  STEP(4, 6)  STEP(8, 5)   STEP(16, 4)
        STEP(32, 3) STEP(64, 2) STEP(128, 1) STEP(256, 0)
        #undef STEP

        for (int p = tid; p < LSEQ; p += blockDim.x) {
            float acc = 0.f;
            #pragma unroll
            for (int o = 0; o < CCH; ++o) {
                #pragma unroll
                for (int k = 0; k < 3; ++k) {
                    const int q = p - k + 1;
                    if (q >= 0 && q < LSEQ)
                        acc += w_first[o * 3 + k] * 0.5f * cur[o][q >> 1];
                }
            }
            g_W[blk][p] = acc;            // transposed layout [c][p]
        }
    } else if (blk == CCH) {
        // U[a][i] = delta(a,i) + V[a][i]
        for (int idx = tid; idx < AA * AA; idx += blockDim.x) {
            const int a = idx / AA, i = idx % AA;
            float v = (a == i) ? 1.f : 0.f;
            if (i != a && i != AA - 1) {
                const int r = (a < i) ? a : i;
                const int c = (a < i) ? i : a;
                float l = lpm[r * AA + c];
                l = fminf(fmaxf(l, 1e-3f), 1.f);
                v = l * pm[r * AA + c];
            }
            g_U[idx] = v;
        }
    } else {
        const int z = blk - (CCH + 1);          // 0..159
        if (tid < 128)
            reinterpret_cast<float4*>(out)[z * 128 + tid] =
                make_float4(0.f, 0.f, 0.f, 0.f);
    }
}

// ---------------------------------------------------------------------------
// Main kernel: grid 1024 = 512 sequences x 2 halves of 256 positions.
// Register-tiled g = X^T W, value-combining butterfly reduce, U-contraction,
// atomicAdd into out. 7 blocks/SM -> single wave.
// ---------------------------------------------------------------------------
__global__ void __launch_bounds__(256, 7)
main_kernel(const float* __restrict__ x, float* __restrict__ out) {
    __shared__ float x_sh[256 * XPAD];      // 21504 B
    __shared__ float W_sh[CCH * 256];       //  8192 B
    __shared__ float g_sh[AA][CCH];         //   640 B

    const int bi   = blockIdx.x;
    const int b    = bi >> 1;
    const int half = bi & 1;
    const int tid  = threadIdx.x;
    const int s    = tid & 31;
    const int w    = tid >> 5;
    const int gq   = w >> 1;                // a-group 0..3 (rows 5gq..5gq+4)
    const int h    = w & 1;                 // c-half 0..1 (cols 4h..4h+3)

    // Stage W chunk [8][256].
    {
        const float4* Wg = reinterpret_cast<const float4*>(g_W);
        #pragma unroll
        for (int it = 0; it < 2; ++it) {
            const int i = tid + it * 256;    // < 512
            const int c = i >> 6, p4 = i & 63;
            reinterpret_cast<float4*>(W_sh)[c * 64 + p4] =
                Wg[c * 128 + half * 64 + p4];
        }
    }

    // Stage x half-chunk: coalesced loads, scatter into padded rows.
    {
        const float4* xg = reinterpret_cast<const float4*>(x)
                         + (size_t)b * 2560 + half * 1280;
        #pragma unroll
        for (int it = 0; it < 5; ++it) {
            const int i = tid + it * 256;    // < 1280
            const float4 v = xg[i];
            const int p  = i / 5;
            const int a0 = (i - p * 5) * 4;
            float* d = &x_sh[p * XPAD + a0];
            d[0] = v.x; d[1] = v.y; d[2] = v.z; d[3] = v.w;
        }
    }
    __syncthreads();

    float acc[5][4];
    #pragma unroll
    for (int m = 0; m < 5; ++m)
        #pragma unroll
        for (int n = 0; n < 4; ++n) acc[m][n] = 0.f;

    // Fixed base pointers; all offsets below are compile-time immediates.
    const float* xp = &x_sh[s * XPAD + gq * 5];
    const float* wp = &W_sh[(h * 4) * 256 + s];
    #pragma unroll
    for (int j = 0; j < 8; ++j) {           // p = 32*j + s
        float xr[5], wr[4];
        #pragma unroll
        for (int m = 0; m < 5; ++m) xr[m] = xp[j * 32 * XPAD + m];
        #pragma unroll
        for (int n = 0; n < 4; ++n) wr[n] = wp[n * 256 + j * 32];
        #pragma unroll
        for (int m = 0; m < 5; ++m)
            #pragma unroll
            for (int n = 0; n < 4; ++n)
                acc[m][n] += xr[m] * wr[n];
    }

    // Value-combining butterfly reduce over lanes (K within the warp).
    // Stage A (off=16): fold n-pairs (0,1) and (2,3): 20 -> 10 values.
    const bool hi16 = (s & 16) != 0;
    const bool hi8  = (s & 8) != 0;
    float r1[5][2];
    #pragma unroll
    for (int m = 0; m < 5; ++m) {
        #pragma unroll
        for (int u = 0; u < 2; ++u) {
            const float a = acc[m][2 * u];
            const float bb = acc[m][2 * u + 1];
            const float keep = hi16 ? bb : a;
            const float send = hi16 ? a : bb;
            r1[m][u] = keep + __shfl_xor_sync(0xffffffffu, send, 16);
        }
    }
    // Stage B (off=8): fold u-pairs: 10 -> 5 values.
    float r2[5];
    #pragma unroll
    for (int m = 0; m < 5; ++m) {
        const float a = r1[m][0];
        const float bb = r1[m][1];
        const float keep = hi8 ? bb : a;
        const float send = hi8 ? a : bb;
        r2[m] = keep + __shfl_xor_sync(0xffffffffu, send, 8);
    }
    // Stages C/D/E: plain butterflies (off 4,2,1) on 5 values.
    #pragma unroll
    for (int m = 0; m < 5; ++m) {
        r2[m] += __shfl_xor_sync(0xffffffffu, r2[m], 4);
        r2[m] += __shfl_xor_sync(0xffffffffu, r2[m], 2);
        r2[m] += __shfl_xor_sync(0xffffffffu, r2[m], 1);
    }
    // Lane (b16,b8) holds acc[m][2*b8+b16] fully reduced. Writers: lane&7==0.
    if ((s & 7) == 0) {
        const int n = 2 * ((s >> 3) & 1) + ((s >> 4) & 1);
        #pragma unroll
        for (int m = 0; m < 5; ++m)
            g_sh[gq * 5 + m][h * 4 + n] = r2[m];
    }
    __syncthreads();

    // out[b,i,c] += sum_a U[a][i] * g[a][c]   (2 halves combine via atomics)
    if (tid < AA * CCH) {
        const int i = tid >> 3;
        const int c = tid & 7;
        float r = 0.f;
        #pragma unroll
        for (int a = 0; a < AA; ++a)
            r += __ldg(&g_U[a * AA + i]) * g_sh[a][c];
        atomicAdd(&out[(size_t)b * (AA * CCH) + tid], r);
    }
}

// ---------------------------------------------------------------------------
extern "C" void kernel_launch(void* const* d_in, const int* in_sizes, int n_in,
                              void* d_out, int out_size) {
    const float* x       = (const float*)d_in[0];
    const float* lpm     = (const float*)d_in[2];
    const float* pm      = (const float*)d_in[3];
    const float* w_first = (const float*)d_in[4];
    const float* w_rest  = (const float*)d_in[5];
    float* out = (float*)d_out;

    precompute_kernel<<<CCH + 1 + 160, 256>>>(lpm, pm, w_first, w_rest, out);
    main_kernel<<<BSEQ * 2, 256>>>(x, out);
}